// round 5
// baseline (speedup 1.0000x reference)
#include <cuda_runtime.h>
#include <cuda_bf16.h>

// Scalar loss accumulator (device global — no allocation allowed).
__device__ double g_loss_acc;

__global__ void zero_acc_kernel() {
    g_loss_acc = 0.0;
}

__global__ void edge_kernel(const float* __restrict__ pos,
                            const int* __restrict__ rows,
                            const int* __restrict__ cols,
                            const int* __restrict__ bond_types,
                            const float* __restrict__ target_lengths,
                            const float* __restrict__ length_adjustment,
                            float* __restrict__ out,
                            int E, int N) {
    __shared__ float s_tgt[5];
    if (threadIdx.x < 5)
        s_tgt[threadIdx.x] = target_lengths[threadIdx.x] + length_adjustment[threadIdx.x];
    __syncthreads();

    int e = blockIdx.x * blockDim.x + threadIdx.x;
    float err = 0.0f;
    if (e < E) {
        int r = rows[e];
        int c = cols[e];
        // Defensive clamp: an out-of-range index becomes a rel-err failure
        // (diagnosable) instead of an illegal memory access.
        r = min(max(r, 0), N - 1);
        c = min(max(c, 0), N - 1);

        const float* pr = pos + 3 * r;
        const float* pc = pos + 3 * c;
        float dx = pr[0] - pc[0];
        float dy = pr[1] - pc[1];
        float dz = pr[2] - pc[2];
        float len = sqrtf(dx * dx + dy * dy + dz * dz);
        len = fmaxf(len, 1e-6f);

        int b = bond_types[e];
        b = min(max(b, 0), 4);
        float tgt = s_tgt[b];

        err = fabsf(len - tgt);

        float ratio = fminf(fmaxf(tgt / len, 0.8f), 1.2f);
        // half-adjustment = bv*(ratio-1)*CORRECTION_FACTOR*0.5 = bv*(ratio-1)*0.05
        float s = (ratio - 1.0f) * 0.05f;
        float ax = dx * s, ay = dy * s, az = dz * s;

        atomicAdd(out + 3 * r + 0,  ax);
        atomicAdd(out + 3 * r + 1,  ay);
        atomicAdd(out + 3 * r + 2,  az);
        atomicAdd(out + 3 * c + 0, -ax);
        atomicAdd(out + 3 * c + 1, -ay);
        atomicAdd(out + 3 * c + 2, -az);
    }

    // Block reduction of the length errors.
    #pragma unroll
    for (int o = 16; o > 0; o >>= 1)
        err += __shfl_down_sync(0xffffffff, err, o);

    __shared__ float warpsum[8];
    int lane = threadIdx.x & 31;
    int wid  = threadIdx.x >> 5;
    if (lane == 0) warpsum[wid] = err;
    __syncthreads();
    if (wid == 0) {
        int nwarps = blockDim.x >> 5;
        float v = (lane < nwarps) ? warpsum[lane] : 0.0f;
        #pragma unroll
        for (int o = 4; o > 0; o >>= 1)
            v += __shfl_down_sync(0xffffffff, v, o);
        if (lane == 0)
            atomicAdd(&g_loss_acc, (double)v);
    }
}

__global__ void finalize_kernel(float* __restrict__ out, int loss_idx, float scale) {
    // loss = mean(err) * CONSTRAINT_WEIGHT = (sum / E) * 0.1
    out[loss_idx] = (float)g_loss_acc * scale;
}

extern "C" void kernel_launch(void* const* d_in, const int* in_sizes, int n_in,
                              void* d_out, int out_size) {
    const float* pos = (const float*)d_in[0];   // [N,3] flattened f32
    const int*   ei  = (const int*)d_in[1];     // [2,E] flattened int32 (JAX x64 disabled)
    const int*   bt  = (const int*)d_in[2];     // [E] int32
    const float* tl  = (const float*)d_in[3];   // [5]
    const float* la  = (const float*)d_in[4];   // [5]
    float*       out = (float*)d_out;

    const int n_pos = in_sizes[0];              // 3*N = 1,500,000
    const int N     = n_pos / 3;                // 500,000
    const int E     = in_sizes[2];              // 8,000,000
    const int* rows = ei;
    const int* cols = ei + E;

    // out[0 .. n_pos) = pos  (then scatter-added below)
    cudaMemcpyAsync(out, pos, (size_t)n_pos * sizeof(float),
                    cudaMemcpyDeviceToDevice);

    zero_acc_kernel<<<1, 1>>>();

    const int threads = 256;
    const int blocks  = (E + threads - 1) / threads;
    edge_kernel<<<blocks, threads>>>(pos, rows, cols, bt, tl, la, out, E, N);

    finalize_kernel<<<1, 1>>>(out, n_pos, 0.1f / (float)E);
}

// round 7
// speedup vs baseline: 2.1472x; 2.1472x over previous
#include <cuda_runtime.h>
#include <cuda_bf16.h>

#define MAX_NODES 524288   // >= 500,000, static scratch (no allocation allowed)

// Statically zero-initialized; every launch leaves these back at zero
// (scratch is reset by the consumer kernel, loss acc by the finalize thread),
// so CUDA-graph replays are deterministic.
__device__ float4 g_scratch[MAX_NODES];   // per-node accumulated half-adjustments
__device__ float4 g_pospad[MAX_NODES];    // pos padded to float4 for 1-LDG gathers
__device__ double g_loss_acc;

// ---------------------------------------------------------------------------
// 1) Pad pos [N,3] -> float4 [N]
// ---------------------------------------------------------------------------
__global__ void pad_pos_kernel(const float* __restrict__ pos, int N) {
    int i = blockIdx.x * blockDim.x + threadIdx.x;
    if (i < N) {
        g_pospad[i] = make_float4(pos[3 * i], pos[3 * i + 1], pos[3 * i + 2], 0.0f);
    }
}

// ---------------------------------------------------------------------------
// 2) Edge kernel: 4 edges per thread, vector index loads, float4 gathers,
//    red.global.add.v4.f32 scatters, block-reduced loss.
// ---------------------------------------------------------------------------
__device__ __forceinline__ void red_add_v4(float4* addr, float a, float b, float c) {
    asm volatile("red.global.add.v4.f32 [%0], {%1, %2, %3, %4};"
                 :: "l"(addr), "f"(a), "f"(b), "f"(c), "f"(0.0f)
                 : "memory");
}

__device__ __forceinline__ float process_edge(int r, int c, int b, int N,
                                              const float* __restrict__ s_tgt) {
    r = min(max(r, 0), N - 1);
    c = min(max(c, 0), N - 1);
    b = min(max(b, 0), 4);

    float4 pr = g_pospad[r];
    float4 pc = g_pospad[c];
    float dx = pr.x - pc.x;
    float dy = pr.y - pc.y;
    float dz = pr.z - pc.z;
    float d2 = fmaxf(dx * dx + dy * dy + dz * dz, 1e-12f);
    float rsq = rsqrtf(d2);
    float len = d2 * rsq;                 // = sqrt(d2) >= 1e-6

    float tgt = s_tgt[b];
    float ratio = fminf(fmaxf(tgt * rsq, 0.8f), 1.2f);
    // half-adjustment = bv * (ratio-1) * CORRECTION_FACTOR * 0.5 = bv*(ratio-1)*0.05
    float s = (ratio - 1.0f) * 0.05f;
    float ax = dx * s, ay = dy * s, az = dz * s;

    red_add_v4(&g_scratch[r],  ax,  ay,  az);
    red_add_v4(&g_scratch[c], -ax, -ay, -az);

    return fabsf(len - tgt);
}

__global__ void edge_kernel(const int* __restrict__ rows,
                            const int* __restrict__ cols,
                            const int* __restrict__ bond_types,
                            const float* __restrict__ target_lengths,
                            const float* __restrict__ length_adjustment,
                            int E, int N) {
    __shared__ float s_tgt[5];
    if (threadIdx.x < 5)
        s_tgt[threadIdx.x] = target_lengths[threadIdx.x] + length_adjustment[threadIdx.x];
    __syncthreads();

    int t = blockIdx.x * blockDim.x + threadIdx.x;
    int base = t * 4;
    float err = 0.0f;

    if (base + 3 < E) {
        int4 r4 = *reinterpret_cast<const int4*>(rows + base);
        int4 c4 = *reinterpret_cast<const int4*>(cols + base);
        int4 b4 = *reinterpret_cast<const int4*>(bond_types + base);
        err += process_edge(r4.x, c4.x, b4.x, N, s_tgt);
        err += process_edge(r4.y, c4.y, b4.y, N, s_tgt);
        err += process_edge(r4.z, c4.z, b4.z, N, s_tgt);
        err += process_edge(r4.w, c4.w, b4.w, N, s_tgt);
    } else {
        for (int e = base; e < E; e++)
            err += process_edge(rows[e], cols[e], bond_types[e], N, s_tgt);
    }

    // Block reduction of the length-error partial sums.
    #pragma unroll
    for (int o = 16; o > 0; o >>= 1)
        err += __shfl_down_sync(0xffffffff, err, o);

    __shared__ float warpsum[8];
    int lane = threadIdx.x & 31;
    int wid  = threadIdx.x >> 5;
    if (lane == 0) warpsum[wid] = err;
    __syncthreads();
    if (wid == 0) {
        int nwarps = blockDim.x >> 5;
        float v = (lane < nwarps) ? warpsum[lane] : 0.0f;
        #pragma unroll
        for (int o = 4; o > 0; o >>= 1)
            v += __shfl_down_sync(0xffffffff, v, o);
        if (lane == 0)
            atomicAdd(&g_loss_acc, (double)v);
    }
}

// ---------------------------------------------------------------------------
// 3) Combine: out = pos + scratch; reset scratch to zero for the next replay;
//    one thread writes the loss and resets the accumulator.
// ---------------------------------------------------------------------------
__global__ void combine_kernel(const float* __restrict__ pos,
                               float* __restrict__ out,
                               int N, int loss_idx, float scale) {
    int i = blockIdx.x * blockDim.x + threadIdx.x;
    if (i < N) {
        float4 s = g_scratch[i];
        out[3 * i + 0] = pos[3 * i + 0] + s.x;
        out[3 * i + 1] = pos[3 * i + 1] + s.y;
        out[3 * i + 2] = pos[3 * i + 2] + s.z;
        g_scratch[i] = make_float4(0.0f, 0.0f, 0.0f, 0.0f);
    }
    if (i == 0) {
        out[loss_idx] = (float)(g_loss_acc) * scale;
        g_loss_acc = 0.0;
    }
}

// ---------------------------------------------------------------------------
extern "C" void kernel_launch(void* const* d_in, const int* in_sizes, int n_in,
                              void* d_out, int out_size) {
    const float* pos = (const float*)d_in[0];   // [N,3] f32
    const int*   ei  = (const int*)d_in[1];     // [2,E] int32
    const int*   bt  = (const int*)d_in[2];     // [E]   int32
    const float* tl  = (const float*)d_in[3];   // [5]
    const float* la  = (const float*)d_in[4];   // [5]
    float*       out = (float*)d_out;

    const int n_pos = in_sizes[0];              // 3*N
    const int N     = n_pos / 3;
    const int E     = in_sizes[2];
    const int* rows = ei;
    const int* cols = ei + E;

    const int threads = 256;

    pad_pos_kernel<<<(N + threads - 1) / threads, threads>>>(pos, N);

    const int nthreads_e = (E + 3) / 4;
    edge_kernel<<<(nthreads_e + threads - 1) / threads, threads>>>(
        rows, cols, bt, tl, la, E, N);

    combine_kernel<<<(N + threads - 1) / threads, threads>>>(
        pos, out, N, n_pos, 0.1f / (float)E);
}